// round 4
// baseline (speedup 1.0000x reference)
#include <cuda_runtime.h>
#include <cuda_fp16.h>

#define N_AG 64
#define HW 8
#define BLK 128

// Batch-invariant weights in constant memory: uniform, compile-time-indexed
// reads -> LDC/uniform-operand FMAs, zero per-lane L1/shared traffic.
__constant__ float cW1[N_AG * HW];
__constant__ float cB1[N_AG * HW];
__constant__ float cW2[N_AG * HW];
__constant__ float cB2[N_AG];
__constant__ float cWc1[2 * HW];   // [0..7]=weight on x_send, [8..15]=x_recv
__constant__ float cBc1[HW];
__constant__ float cWc2[HW];

__device__ __forceinline__ half2 tanh_h2(half2 x) {
    half2 y;
    asm("tanh.approx.f16x2 %0, %1;"
        : "=r"(reinterpret_cast<unsigned&>(y))
        : "r"(reinterpret_cast<unsigned const&>(x)));
    return y;
}

// tanh of two fp32 values via one f16x2 MUFU op; returns fp32 pair.
__device__ __forceinline__ float2 tanh_pair(float a, float b) {
    half2 p = tanh_h2(__floats2half2_rn(a, b));  // .x=a, .y=b
    return __half22float2(p);                    // .x=tanh(a), .y=tanh(b)
}

// Coupling contribution for edge (xs -> xn); bc2 cancels in the ring difference.
__device__ __forceinline__ float coupling(float xs, float xn) {
    float t[HW];
    #pragma unroll
    for (int h = 0; h < HW; h++)
        t[h] = fmaf(xs, cWc1[h], fmaf(xn, cWc1[HW + h], cBc1[h]));
    float cc = 0.f;
    #pragma unroll
    for (int h = 0; h < HW; h += 2) {
        float2 f = tanh_pair(t[h], t[h + 1]);
        cc = fmaf(f.x, cWc2[h], fmaf(f.y, cWc2[h + 1], cc));
    }
    return cc;
}

__global__ void __launch_bounds__(BLK)
ode_kernel(const float* __restrict__ x, float* __restrict__ out, int nrows)
{
    int row = blockIdx.x * BLK + threadIdx.x;
    if (row >= nrows) return;

    const float4* xr   = (const float4*)(x   + (size_t)row * N_AG);
    float4*       outr = (float4*)      (out + (size_t)row * N_AG);

    float4 first = xr[0];

    // Ring: interactions[n] = contrib[(n-1) mod 64] - contrib[n].
    // Seed carry with contrib[63] = g(x[63], x[0]).
    float cprev = coupling(xr[15].w, first.x);

    float4 cur = first;
    #pragma unroll 4
    for (int c = 0; c < 16; c++) {
        float4 nxt = (c == 15) ? first : xr[c + 1];
        float xv[5];
        xv[0] = cur.x; xv[1] = cur.y; xv[2] = cur.z; xv[3] = cur.w; xv[4] = nxt.x;

        float res[4];
        #pragma unroll
        for (int j = 0; j < 4; j++) {
            int n = c * 4 + j;
            float xs = xv[j], xn = xv[j + 1];

            float cc = coupling(xs, xn);

            // intrinsic per-agent MLP (args + dot fp32, tanh f16x2)
            float t[HW];
            #pragma unroll
            for (int h = 0; h < HW; h++)
                t[h] = fmaf(xs, cW1[n * HW + h], cB1[n * HW + h]);
            float acc = cB2[n];
            #pragma unroll
            for (int h = 0; h < HW; h += 2) {
                float2 f = tanh_pair(t[h], t[h + 1]);
                acc = fmaf(f.x, cW2[n * HW + h], fmaf(f.y, cW2[n * HW + h + 1], acc));
            }

            res[j] = acc + cprev - cc;
            cprev = cc;
        }

        float4 o;
        o.x = res[0]; o.y = res[1]; o.z = res[2]; o.w = res[3];
        outr[c] = o;
        cur = nxt;
    }
}

extern "C" void kernel_launch(void* const* d_in, const int* in_sizes, int n_in,
                              void* d_out, int out_size)
{
    // metadata order: x, W1, b1, W2, b2, Wc1, bc1, Wc2, bc2, send_idx, recv_idx
    const float* x = (const float*)d_in[0];
    float* out = (float*)d_out;

    // Device-to-device async copies into constant bank (graph-capturable, no alloc)
    cudaMemcpyToSymbolAsync(cW1,  d_in[1], N_AG * HW * sizeof(float), 0, cudaMemcpyDeviceToDevice);
    cudaMemcpyToSymbolAsync(cB1,  d_in[2], N_AG * HW * sizeof(float), 0, cudaMemcpyDeviceToDevice);
    cudaMemcpyToSymbolAsync(cW2,  d_in[3], N_AG * HW * sizeof(float), 0, cudaMemcpyDeviceToDevice);
    cudaMemcpyToSymbolAsync(cB2,  d_in[4], N_AG * sizeof(float),      0, cudaMemcpyDeviceToDevice);
    cudaMemcpyToSymbolAsync(cWc1, d_in[5], 2 * HW * sizeof(float),    0, cudaMemcpyDeviceToDevice);
    cudaMemcpyToSymbolAsync(cBc1, d_in[6], HW * sizeof(float),        0, cudaMemcpyDeviceToDevice);
    cudaMemcpyToSymbolAsync(cWc2, d_in[7], HW * sizeof(float),        0, cudaMemcpyDeviceToDevice);
    // bc2 (d_in[8]) cancels; send/recv idx (d_in[9..10]) are the fixed ring.

    int nrows = in_sizes[0] / N_AG;
    int grid = (nrows + BLK - 1) / BLK;
    ode_kernel<<<grid, BLK>>>(x, out, nrows);
}

// round 5
// speedup vs baseline: 1.1495x; 1.1495x over previous
#include <cuda_runtime.h>
#include <cuda_fp16.h>

#define N_AG 64
#define HW 8
#define BLK 128
#define HALF_AG 32

// Single packed constant block: W1[512] B1[512] W2[512] B2[64] Wc1[16] Bc1[8] Wc2[8]
#define OFF_W1  0
#define OFF_B1  512
#define OFF_W2  1024
#define OFF_B2  1536
#define OFF_WC1 1600
#define OFF_BC1 1616
#define OFF_WC2 1624
#define W_TOT   1632

__constant__ float cw[W_TOT];
__device__ float gStage[W_TOT];

__global__ void gather_weights(const float* __restrict__ W1, const float* __restrict__ B1,
                               const float* __restrict__ W2, const float* __restrict__ B2,
                               const float* __restrict__ Wc1, const float* __restrict__ Bc1,
                               const float* __restrict__ Wc2)
{
    int t = threadIdx.x;           // 512 threads, 1 block
    gStage[OFF_W1 + t] = W1[t];
    gStage[OFF_B1 + t] = B1[t];
    gStage[OFF_W2 + t] = W2[t];
    if (t < 64) gStage[OFF_B2 + t] = B2[t];
    if (t < 16) gStage[OFF_WC1 + t] = Wc1[t];
    if (t < 8)  gStage[OFF_BC1 + t] = Bc1[t];
    if (t < 8)  gStage[OFF_WC2 + t] = Wc2[t];
}

__device__ __forceinline__ half2 tanh_h2(half2 x) {
    half2 y;
    asm("tanh.approx.f16x2 %0, %1;"
        : "=r"(reinterpret_cast<unsigned&>(y))
        : "r"(reinterpret_cast<unsigned const&>(x)));
    return y;
}

// tanh of two fp32 values via one f16x2 MUFU op; returns fp32 pair.
__device__ __forceinline__ float2 tanh_pair(float a, float b) {
    half2 p = tanh_h2(__floats2half2_rn(a, b));
    return __half22float2(p);
}

// Coupling contribution for edge (xs -> xn); bc2 cancels in the ring difference.
__device__ __forceinline__ float coupling(float xs, float xn) {
    float t[HW];
    #pragma unroll
    for (int h = 0; h < HW; h++)
        t[h] = fmaf(xs, cw[OFF_WC1 + h], fmaf(xn, cw[OFF_WC1 + HW + h], cw[OFF_BC1 + h]));
    float cc = 0.f;
    #pragma unroll
    for (int h = 0; h < HW; h += 2) {
        float2 f = tanh_pair(t[h], t[h + 1]);
        cc = fmaf(f.x, cw[OFF_WC2 + h], fmaf(f.y, cw[OFF_WC2 + h + 1], cc));
    }
    return cc;
}

__global__ void __launch_bounds__(BLK, 14)
ode_kernel(const float* __restrict__ x, float* __restrict__ out, int nrows)
{
    // Block-uniform half selection keeps every weight index warp-uniform
    // (preserves LDCU/uniform-port constant reads); lanes = consecutive rows.
    int row  = (blockIdx.x >> 1) * BLK + threadIdx.x;
    int half = blockIdx.x & 1;
    if (row >= nrows) return;

    const float* xrow = x + (size_t)row * N_AG;
    const float4* xr   = (const float4*)xrow + half * 8;
    float4*       outr = (float4*)(out + (size_t)row * N_AG) + half * 8;

    int n0 = half * HALF_AG;
    // Wrap scalars from the other half of the ring
    float xNext = xrow[(n0 + HALF_AG) & 63];  // x[(n0+32) mod 64]
    float xPrev = xrow[(n0 + 63) & 63];       // x[(n0-1) mod 64]

    float4 q0 = xr[0];
    // interactions[n] = contrib[n-1] - contrib[n]; seed carry with contrib[n0-1]
    float cprev = coupling(xPrev, q0.x);

    float4 cur = q0;
    #pragma unroll 4
    for (int c = 0; c < 8; c++) {
        float4 nxt;
        float nxt0;
        if (c < 7) { nxt = xr[c + 1]; nxt0 = nxt.x; } else { nxt0 = xNext; }
        float xv[5];
        xv[0] = cur.x; xv[1] = cur.y; xv[2] = cur.z; xv[3] = cur.w; xv[4] = nxt0;

        float res[4];
        #pragma unroll
        for (int j = 0; j < 4; j++) {
            int n = n0 + c * 4 + j;
            float xs = xv[j], xn = xv[j + 1];

            float cc = coupling(xs, xn);

            // intrinsic per-agent MLP (pre-activations + dots fp32, tanh f16x2)
            float t[HW];
            #pragma unroll
            for (int h = 0; h < HW; h++)
                t[h] = fmaf(xs, cw[OFF_W1 + n * HW + h], cw[OFF_B1 + n * HW + h]);
            float acc = cw[OFF_B2 + n];
            #pragma unroll
            for (int h = 0; h < HW; h += 2) {
                float2 f = tanh_pair(t[h], t[h + 1]);
                acc = fmaf(f.x, cw[OFF_W2 + n * HW + h],
                      fmaf(f.y, cw[OFF_W2 + n * HW + h + 1], acc));
            }

            res[j] = acc + cprev - cc;
            cprev = cc;
        }

        float4 o;
        o.x = res[0]; o.y = res[1]; o.z = res[2]; o.w = res[3];
        outr[c] = o;
        if (c < 7) cur = nxt;
    }
}

extern "C" void kernel_launch(void* const* d_in, const int* in_sizes, int n_in,
                              void* d_out, int out_size)
{
    // metadata order: x, W1, b1, W2, b2, Wc1, bc1, Wc2, bc2, send_idx, recv_idx
    const float* x = (const float*)d_in[0];
    float* out = (float*)d_out;

    // 2 graph nodes for weight staging instead of 7 memcpys
    gather_weights<<<1, 512>>>((const float*)d_in[1], (const float*)d_in[2],
                               (const float*)d_in[3], (const float*)d_in[4],
                               (const float*)d_in[5], (const float*)d_in[6],
                               (const float*)d_in[7]);
    void* stagePtr = nullptr;
    cudaGetSymbolAddress(&stagePtr, gStage);
    cudaMemcpyToSymbolAsync(cw, stagePtr, W_TOT * sizeof(float), 0,
                            cudaMemcpyDeviceToDevice);

    int nrows = in_sizes[0] / N_AG;
    int gridPairs = (nrows + BLK - 1) / BLK;   // blocks per half
    ode_kernel<<<gridPairs * 2, BLK>>>(x, out, nrows);
}

// round 6
// speedup vs baseline: 1.1628x; 1.0116x over previous
#include <cuda_runtime.h>
#include <cuda_fp16.h>

#define N_AG 64
#define HW 8
#define BLK 128
#define SEG_AG 16          // agents per thread (quarter-ring split)

// Packed coupling pre-activation weights, h-paired f16x2 (built per launch)
__device__ uint4 gA0, gA1, gCB;

__global__ void pack_coup(const float* __restrict__ Wc1, const float* __restrict__ Bc1)
{
    if (threadIdx.x == 0) {
        uint4 a0, a1, cb;
        #pragma unroll
        for (int p = 0; p < 4; p++) {
            ((half2*)&a0)[p] = __floats2half2_rn(Wc1[2*p],     Wc1[2*p + 1]);     // x_send w
            ((half2*)&a1)[p] = __floats2half2_rn(Wc1[8 + 2*p], Wc1[8 + 2*p + 1]); // x_recv w
            ((half2*)&cb)[p] = __floats2half2_rn(Bc1[2*p],     Bc1[2*p + 1]);
        }
        gA0 = a0; gA1 = a1; gCB = cb;
    }
}

__device__ __forceinline__ half2 tanh_h2(half2 x) {
    half2 y;
    asm("tanh.approx.f16x2 %0, %1;"
        : "=r"(reinterpret_cast<unsigned&>(y))
        : "r"(reinterpret_cast<unsigned const&>(x)));
    return y;
}

// fp32 tanh-pair via one f16x2 MUFU (intrinsic path: fp32 pre-act, packed tanh)
__device__ __forceinline__ float2 tanh_pair(float a, float b) {
    return __half22float2(tanh_h2(__floats2half2_rn(a, b)));
}

// Coupling for one edge, pre-activation in HFMA2 on h-paired weights.
// s2/n2 are dup-packed (x,x) halves of x_send / x_recv.
__device__ __forceinline__ float coup(half2 s2, half2 n2,
                                      const half2* A0, const half2* A1,
                                      const half2* CB, const float* CW)
{
    float cc = 0.f;
    #pragma unroll
    for (int p = 0; p < 4; p++) {
        half2 t = __hfma2(s2, A0[p], __hfma2(n2, A1[p], CB[p]));
        float2 g = __half22float2(tanh_h2(t));
        cc = fmaf(g.x, CW[2*p], fmaf(g.y, CW[2*p + 1], cc));
    }
    return cc;
}

__global__ void __launch_bounds__(BLK)
ode_kernel(const float* __restrict__ x,
           const float* __restrict__ W1, const float* __restrict__ B1,
           const float* __restrict__ W2, const float* __restrict__ B2,
           const float* __restrict__ Wc2,
           float* __restrict__ out, int nrows)
{
    // Per-agent weights in shared: wide uniform-broadcast LDS.128 (floor 2)
    __shared__ float4 sW1[N_AG * 2], sB1[N_AG * 2], sW2[N_AG * 2];
    __shared__ float  sB2[N_AG];

    int tid = threadIdx.x;
    {
        const float4* gW1 = (const float4*)W1;
        const float4* gB1 = (const float4*)B1;
        const float4* gW2 = (const float4*)W2;
        sW1[tid] = gW1[tid];
        sB1[tid] = gB1[tid];
        sW2[tid] = gW2[tid];
        if (tid < N_AG) sB2[tid] = B2[tid];
    }

    // Hoist coupling constants to registers (loaded once, L1-cached uniform)
    half2 A0[4], A1[4], CB[4];
    {
        uint4 ua = gA0, ub = gA1, uc = gCB;
        #pragma unroll
        for (int p = 0; p < 4; p++) {
            A0[p] = ((half2*)&ua)[p];
            A1[p] = ((half2*)&ub)[p];
            CB[p] = ((half2*)&uc)[p];
        }
    }
    float CW[8];
    {
        float4 c0 = ((const float4*)Wc2)[0], c1 = ((const float4*)Wc2)[1];
        CW[0]=c0.x; CW[1]=c0.y; CW[2]=c0.z; CW[3]=c0.w;
        CW[4]=c1.x; CW[5]=c1.y; CW[6]=c1.z; CW[7]=c1.w;
    }
    __syncthreads();

    int row = (blockIdx.x >> 2) * BLK + tid;   // block-uniform segment id keeps
    int seg = blockIdx.x & 3;                  // all weight indices warp-uniform
    if (row >= nrows) return;

    const float* xrow = x + (size_t)row * N_AG;
    int n0 = seg * SEG_AG;

    // Front-batch the segment's x quads + ring boundary scalars
    const float4* xr   = (const float4*)xrow + (n0 >> 2);
    float4 q[4];
    q[0] = xr[0]; q[1] = xr[1]; q[2] = xr[2]; q[3] = xr[3];
    float xPrev = xrow[(n0 + 63) & 63];
    float xNext = xrow[(n0 + SEG_AG) & 63];

    float4* outr = (float4*)(out + (size_t)row * N_AG) + (n0 >> 2);

    // interactions[n] = contrib[n-1] - contrib[n]; seed carry with contrib[n0-1]
    half2 sh = __float2half2_rn(xPrev);
    half2 nh = __float2half2_rn(q[0].x);
    float cprev = coup(sh, nh, A0, A1, CB, CW);

    #pragma unroll
    for (int c = 0; c < 4; c++) {
        float xv[5];
        xv[0] = q[c].x; xv[1] = q[c].y; xv[2] = q[c].z; xv[3] = q[c].w;
        xv[4] = (c < 3) ? q[c + 1].x : xNext;

        float res[4];
        #pragma unroll
        for (int j = 0; j < 4; j++) {
            int n = n0 + c * 4 + j;
            float xs = xv[j];

            // coupling edge n -> n+1 (carry packed halves: send = last recv)
            sh = nh;
            nh = __float2half2_rn(xv[j + 1]);
            float cc = coup(sh, nh, A0, A1, CB, CW);

            // intrinsic per-agent MLP: fp32 pre-act + dot, f16x2 tanh
            float4 w1a = sW1[n*2], w1b = sW1[n*2+1];
            float4 b1a = sB1[n*2], b1b = sB1[n*2+1];
            float4 w2a = sW2[n*2], w2b = sW2[n*2+1];
            float acc = sB2[n];
            float2 f;
            f = tanh_pair(fmaf(xs, w1a.x, b1a.x), fmaf(xs, w1a.y, b1a.y));
            acc = fmaf(f.x, w2a.x, fmaf(f.y, w2a.y, acc));
            f = tanh_pair(fmaf(xs, w1a.z, b1a.z), fmaf(xs, w1a.w, b1a.w));
            acc = fmaf(f.x, w2a.z, fmaf(f.y, w2a.w, acc));
            f = tanh_pair(fmaf(xs, w1b.x, b1b.x), fmaf(xs, w1b.y, b1b.y));
            acc = fmaf(f.x, w2b.x, fmaf(f.y, w2b.y, acc));
            f = tanh_pair(fmaf(xs, w1b.z, b1b.z), fmaf(xs, w1b.w, b1b.w));
            acc = fmaf(f.x, w2b.z, fmaf(f.y, w2b.w, acc));

            res[j] = acc + cprev - cc;
            cprev = cc;
        }

        float4 o;
        o.x = res[0]; o.y = res[1]; o.z = res[2]; o.w = res[3];
        outr[c] = o;
    }
}

extern "C" void kernel_launch(void* const* d_in, const int* in_sizes, int n_in,
                              void* d_out, int out_size)
{
    // metadata order: x, W1, b1, W2, b2, Wc1, bc1, Wc2, bc2, send_idx, recv_idx
    const float* x = (const float*)d_in[0];
    float* out = (float*)d_out;

    pack_coup<<<1, 32>>>((const float*)d_in[5], (const float*)d_in[6]);

    int nrows = in_sizes[0] / N_AG;
    int grid = ((nrows + BLK - 1) / BLK) * 4;   // 4 ring segments per row-block
    ode_kernel<<<grid, BLK>>>(x,
                              (const float*)d_in[1], (const float*)d_in[2],
                              (const float*)d_in[3], (const float*)d_in[4],
                              (const float*)d_in[7],
                              out, nrows);
}